// round 11
// baseline (speedup 1.0000x reference)
#include <cuda_runtime.h>
#include <cuda_fp16.h>
#include <math.h>

// BilateralSlice: out[b,c,i,j] = trilinear(grid[b,c, h(j), w(i), d(guide[b,i,j])])
// Shapes: grid (4,12,16,16,8) f32, guide (4,1,1024,1024) f32, out (4,12,1024,1024) f32.
//
// R11 = R9 mapping (two CTAs/row, 2 px/thread, best measured) + fp16 HFMA2
// accumulation: the 4-corner convex combination is computed in __half2
// (24 HFMA2/px) instead of cvt-to-f32 + FFMA (48 F2F + 48 FFMA/px). Only the
// final 12 F2F per pixel remain for the f32 stores.

#define CC   12
#define HG   16
#define DG   8
#define HH   1024
#define WW_  1024

#define DSTRIDE_H 12          // halves per d
#define HSTRIDE_H 112         // halves per h (96 + 16 pad)
#define DSTRIDE_B 24          // bytes
#define HSTRIDE_B 224         // bytes
#define NSLICE    9           // h-slices per half-row

__device__ __forceinline__ void corner_acc_h(const char* sb, int off, __half2 w2, __half2* acc)
{
    uint2 p0 = *(const uint2*)(sb + off);        // halves c0..c3
    uint2 p1 = *(const uint2*)(sb + off + 8);    // c4..c7
    uint2 p2 = *(const uint2*)(sb + off + 16);   // c8..c11
    acc[0] = __hfma2(*(const __half2*)&p0.x, w2, acc[0]);
    acc[1] = __hfma2(*(const __half2*)&p0.y, w2, acc[1]);
    acc[2] = __hfma2(*(const __half2*)&p1.x, w2, acc[2]);
    acc[3] = __hfma2(*(const __half2*)&p1.y, w2, acc[3]);
    acc[4] = __hfma2(*(const __half2*)&p2.x, w2, acc[4]);
    acc[5] = __hfma2(*(const __half2*)&p2.y, w2, acc[5]);
}

__global__ void __launch_bounds__(256, 4)
bslice_kernel(const float* __restrict__ grid,
              const float* __restrict__ guide,
              float* __restrict__ out)
{
    __shared__ __half sh[NSLICE * HSTRIDE_H];   // 1008 halves = 2016 B
    const char* sb = (const char*)sh;

    const int half = blockIdx.x & 1;
    const int i    = blockIdx.x >> 1;       // image row
    const int b    = blockIdx.y;
    const int t    = threadIdx.x;
    const int hbase = half * 7;             // h-slices [hbase, hbase+8]

    // ---- w cell for this row (constant across the row) ----
    const float wwf = (float)i * (15.0f / 1023.0f);
    int w0 = (int)wwf; if (w0 > 15) w0 = 15;
    int w1 = w0 + 1;   if (w1 > 15) w1 = 15;
    const float fw = wwf - (float)w0;

    // ---- Stage w-interpolated slab (fp32 lerp, fp16 store): 216 groups ----
    const float4* g4 = (const float4*)grid;
    if (t < 216) {                          // 12c * 9h * 2 d-quads
        int c   = t / 18;
        int rem = t - c * 18;
        int h   = rem >> 1;
        int dq  = rem & 1;
        int base = ((b * CC + c) * HG + (hbase + h)) * 32;  // float4 off of [b,c,hg,0,0]
        float4 a  = g4[base + w0 * 2 + dq];
        float4 bb = g4[base + w1 * 2 + dq];
        int so = h * HSTRIDE_H + (dq * 4) * DSTRIDE_H + c;
        sh[so]                 = __float2half_rn(fmaf(fw, bb.x - a.x, a.x));
        sh[so + DSTRIDE_H]     = __float2half_rn(fmaf(fw, bb.y - a.y, a.y));
        sh[so + 2 * DSTRIDE_H] = __float2half_rn(fmaf(fw, bb.z - a.z, a.z));
        sh[so + 3 * DSTRIDE_H] = __float2half_rn(fmaf(fw, bb.w - a.w, a.w));
    }
    __syncthreads();

    // ---- Thread owns 2 consecutive columns ----
    const int j0 = half * 512 + t * 2;

    float2 gv = *(const float2*)(guide + ((size_t)b * HH + i) * WW_ + j0);
    float ga[2] = {gv.x, gv.y};

    float res[24];                          // res[c*2 + jj]
    #pragma unroll
    for (int jj = 0; jj < 2; jj++) {
        float hhf = (float)(j0 + jj) * (15.0f / 1023.0f);
        int h0 = (int)hhf; if (h0 > 15) h0 = 15;
        int h1 = h0 + 1;   if (h1 > 15) h1 = 15;
        const float fhj = hhf - (float)h0;
        const int ho0 = (h0 - hbase) * HSTRIDE_B;
        const int ho1 = (h1 - hbase) * HSTRIDE_B;

        float dc  = ga[jj] * 7.0f;
        float dfl = floorf(dc);
        dfl = fminf(fmaxf(dfl, 0.0f), 7.0f);
        int d0 = (int)dfl;
        int d1 = d0 + 1; if (d1 > 7) d1 = 7;
        float dw = fminf(fmaxf(dc - dfl, 0.0f), 1.0f);

        const __half2 w00 = __float2half2_rn((1.0f - fhj) * (1.0f - dw));
        const __half2 w01 = __float2half2_rn((1.0f - fhj) * dw);
        const __half2 w10 = __float2half2_rn(fhj * (1.0f - dw));
        const __half2 w11 = __float2half2_rn(fhj * dw);

        __half2 acc[6];
        #pragma unroll
        for (int k = 0; k < 6; k++) acc[k] = __half2half2(__ushort_as_half(0));

        corner_acc_h(sb, ho0 + d0 * DSTRIDE_B, w00, acc);
        corner_acc_h(sb, ho0 + d1 * DSTRIDE_B, w01, acc);
        corner_acc_h(sb, ho1 + d0 * DSTRIDE_B, w10, acc);
        corner_acc_h(sb, ho1 + d1 * DSTRIDE_B, w11, acc);

        #pragma unroll
        for (int k = 0; k < 6; k++) {
            float2 f = __half22float2(acc[k]);
            res[(2 * k)     * 2 + jj] = f.x;
            res[(2 * k + 1) * 2 + jj] = f.y;
        }
    }

    // ---- Coalesced float2 stores: 12 channels ----
    #pragma unroll
    for (int c = 0; c < 12; c++) {
        float2 o = make_float2(res[c * 2 + 0], res[c * 2 + 1]);
        *(float2*)(out + (((size_t)b * CC + c) * HH + i) * WW_ + j0) = o;
    }
}

extern "C" void kernel_launch(void* const* d_in, const int* in_sizes, int n_in,
                              void* d_out, int out_size)
{
    const float* grid  = (const float*)d_in[0];
    const float* guide = (const float*)d_in[1];
    float* out = (float*)d_out;

    dim3 gr(HH * 2, 4);                     // two CTAs per (row, batch)
    bslice_kernel<<<gr, 256>>>(grid, guide, out);
}

// round 14
// speedup vs baseline: 1.3830x; 1.3830x over previous
#include <cuda_runtime.h>
#include <cuda_fp16.h>
#include <math.h>

// BilateralSlice: out[b,c,i,j] = trilinear(grid[b,c, h(j), w(i), d(guide[b,i,j])])
// Shapes: grid (4,12,16,16,8) f32, guide (4,1,1024,1024) f32, out (4,12,1024,1024) f32.
//
// R12 = R9 mapping (two CTAs/row, 2 px/thread, fp16 w-lerped slab) with the
// d-lerp done in __half2 (HSUB2+HFMA2 on loaded words) and only the h-blend in
// fp32. Halves the F2F conversions and fp32 FMAs of R9 (~84 vs ~108 issue
// slots/px). All intermediates are named scalars (no arrays through pointers)
// to avoid the local-memory demotion that sank R11.

#define CC   12
#define HG   16
#define DG   8
#define HH   1024
#define WW_  1024

#define DSTRIDE_H 12          // halves per d
#define HSTRIDE_H 112         // halves per h (96 + 16 pad)
#define DSTRIDE_B 24          // bytes
#define HSTRIDE_B 224         // bytes
#define NSLICE    9           // h-slices per half-row

// d-lerp for two channel pairs packed in uint2 (4 channels): r = a0 + dw*(a1-a0)
__device__ __forceinline__ void dlerp2(uint2 u0, uint2 u1, __half2 dw2,
                                       __half2& r0, __half2& r1)
{
    __half2 a0 = *(const __half2*)&u0.x;
    __half2 a1 = *(const __half2*)&u1.x;
    r0 = __hfma2(__hsub2(a1, a0), dw2, a0);
    __half2 b0 = *(const __half2*)&u0.y;
    __half2 b1 = *(const __half2*)&u1.y;
    r1 = __hfma2(__hsub2(b1, b0), dw2, b0);
}

__global__ void __launch_bounds__(256, 4)
bslice_kernel(const float* __restrict__ grid,
              const float* __restrict__ guide,
              float* __restrict__ out)
{
    __shared__ __half sh[NSLICE * HSTRIDE_H];   // 1008 halves = 2016 B
    const char* sb = (const char*)sh;

    const int half = blockIdx.x & 1;
    const int i    = blockIdx.x >> 1;       // image row
    const int b    = blockIdx.y;
    const int t    = threadIdx.x;
    const int hbase = half * 7;             // h-slices [hbase, hbase+8]

    // ---- w cell for this row (constant across the row) ----
    const float wwf = (float)i * (15.0f / 1023.0f);
    int w0 = (int)wwf; if (w0 > 15) w0 = 15;
    int w1 = w0 + 1;   if (w1 > 15) w1 = 15;
    const float fw = wwf - (float)w0;

    // ---- Stage w-interpolated slab (fp32 lerp, fp16 store): 216 groups ----
    const float4* g4 = (const float4*)grid;
    if (t < 216) {                          // 12c * 9h * 2 d-quads
        int c   = t / 18;
        int rem = t - c * 18;
        int h   = rem >> 1;
        int dq  = rem & 1;
        int base = ((b * CC + c) * HG + (hbase + h)) * 32;  // float4 off of [b,c,hg,0,0]
        float4 a  = g4[base + w0 * 2 + dq];
        float4 bb = g4[base + w1 * 2 + dq];
        int so = h * HSTRIDE_H + (dq * 4) * DSTRIDE_H + c;
        sh[so]                 = __float2half_rn(fmaf(fw, bb.x - a.x, a.x));
        sh[so + DSTRIDE_H]     = __float2half_rn(fmaf(fw, bb.y - a.y, a.y));
        sh[so + 2 * DSTRIDE_H] = __float2half_rn(fmaf(fw, bb.z - a.z, a.z));
        sh[so + 3 * DSTRIDE_H] = __float2half_rn(fmaf(fw, bb.w - a.w, a.w));
    }
    __syncthreads();

    // ---- Thread owns 2 consecutive columns ----
    const int j0 = half * 512 + t * 2;

    float2 gv = *(const float2*)(guide + ((size_t)b * HH + i) * WW_ + j0);
    float ga[2] = {gv.x, gv.y};

    float res[24];                          // res[c*2 + jj], constant indices only
    #pragma unroll
    for (int jj = 0; jj < 2; jj++) {
        float hhf = (float)(j0 + jj) * (15.0f / 1023.0f);
        int h0 = (int)hhf; if (h0 > 15) h0 = 15;
        int h1 = h0 + 1;   if (h1 > 15) h1 = 15;
        const float fhj = hhf - (float)h0;
        const int ho0 = (h0 - hbase) * HSTRIDE_B;
        const int ho1 = (h1 - hbase) * HSTRIDE_B;

        float dc  = ga[jj] * 7.0f;
        float dfl = floorf(dc);
        dfl = fminf(fmaxf(dfl, 0.0f), 7.0f);
        int d0 = (int)dfl;
        int d1 = d0 + 1; if (d1 > 7) d1 = 7;
        float dw = fminf(fmaxf(dc - dfl, 0.0f), 1.0f);
        const __half2 dw2 = __float2half2_rn(dw);

        const char* pA0 = sb + ho0 + d0 * DSTRIDE_B;   // (h0, d0)
        const char* pA1 = sb + ho0 + d1 * DSTRIDE_B;   // (h0, d1)
        const char* pB0 = sb + ho1 + d0 * DSTRIDE_B;   // (h1, d0)
        const char* pB1 = sb + ho1 + d1 * DSTRIDE_B;   // (h1, d1)

        #pragma unroll
        for (int qq = 0; qq < 3; qq++) {
            uint2 uA0 = *(const uint2*)(pA0 + 8 * qq);
            uint2 uA1 = *(const uint2*)(pA1 + 8 * qq);
            uint2 uB0 = *(const uint2*)(pB0 + 8 * qq);
            uint2 uB1 = *(const uint2*)(pB1 + 8 * qq);

            __half2 da0, da1, db0, db1;
            dlerp2(uA0, uA1, dw2, da0, da1);   // d-lerp at h0
            dlerp2(uB0, uB1, dw2, db0, db1);   // d-lerp at h1

            float2 fa0 = __half22float2(da0);
            float2 fb0 = __half22float2(db0);
            float2 fa1 = __half22float2(da1);
            float2 fb1 = __half22float2(db1);

            const int c = qq * 4;
            res[(c + 0) * 2 + jj] = fmaf(fhj, fb0.x - fa0.x, fa0.x);
            res[(c + 1) * 2 + jj] = fmaf(fhj, fb0.y - fa0.y, fa0.y);
            res[(c + 2) * 2 + jj] = fmaf(fhj, fb1.x - fa1.x, fa1.x);
            res[(c + 3) * 2 + jj] = fmaf(fhj, fb1.y - fa1.y, fa1.y);
        }
    }

    // ---- Coalesced float2 stores: 12 channels ----
    #pragma unroll
    for (int c = 0; c < 12; c++) {
        float2 o = make_float2(res[c * 2 + 0], res[c * 2 + 1]);
        *(float2*)(out + (((size_t)b * CC + c) * HH + i) * WW_ + j0) = o;
    }
}

extern "C" void kernel_launch(void* const* d_in, const int* in_sizes, int n_in,
                              void* d_out, int out_size)
{
    const float* grid  = (const float*)d_in[0];
    const float* guide = (const float*)d_in[1];
    float* out = (float*)d_out;

    dim3 gr(HH * 2, 4);                     // two CTAs per (row, batch)
    bslice_kernel<<<gr, 256>>>(grid, guide, out);
}

// round 15
// speedup vs baseline: 1.4937x; 1.0801x over previous
#include <cuda_runtime.h>
#include <cuda_fp16.h>
#include <math.h>

// BilateralSlice: out[b,c,i,j] = trilinear(grid[b,c, h(j), w(i), d(guide[b,i,j])])
// Shapes: grid (4,12,16,16,8) f32, guide (4,1,1024,1024) f32, out (4,12,1024,1024) f32.
//
// R15 = R12 (two CTAs/row, 2 px/thread, fp16 w-lerped slab, half2 d-lerp)
// with the h-blend ALSO in half2 (6x HSUB2+HFMA2 per px) and only the final
// 12 values converted to fp32 for the stores. Removes 24 fp32 ops + 12 F2F
// per pixel vs R12. Dead d-clamps dropped (guide in [0,1)).

#define CC   12
#define HG   16
#define DG   8
#define HH   1024
#define WW_  1024

#define DSTRIDE_H 12          // halves per d
#define HSTRIDE_H 112         // halves per h (96 + 16 pad)
#define DSTRIDE_B 24          // bytes
#define HSTRIDE_B 224         // bytes
#define NSLICE    9           // h-slices per half-row

// d-lerp for two channel pairs packed in uint2 (4 channels): r = a0 + dw*(a1-a0)
__device__ __forceinline__ void dlerp2(uint2 u0, uint2 u1, __half2 dw2,
                                       __half2& r0, __half2& r1)
{
    __half2 a0 = *(const __half2*)&u0.x;
    __half2 a1 = *(const __half2*)&u1.x;
    r0 = __hfma2(__hsub2(a1, a0), dw2, a0);
    __half2 b0 = *(const __half2*)&u0.y;
    __half2 b1 = *(const __half2*)&u1.y;
    r1 = __hfma2(__hsub2(b1, b0), dw2, b0);
}

__global__ void __launch_bounds__(256, 4)
bslice_kernel(const float* __restrict__ grid,
              const float* __restrict__ guide,
              float* __restrict__ out)
{
    __shared__ __half sh[NSLICE * HSTRIDE_H];   // 1008 halves = 2016 B
    const char* sb = (const char*)sh;

    const int half = blockIdx.x & 1;
    const int i    = blockIdx.x >> 1;       // image row
    const int b    = blockIdx.y;
    const int t    = threadIdx.x;
    const int hbase = half * 7;             // h-slices [hbase, hbase+8]

    // ---- w cell for this row (constant across the row) ----
    const float wwf = (float)i * (15.0f / 1023.0f);
    int w0 = (int)wwf; if (w0 > 15) w0 = 15;
    int w1 = w0 + 1;   if (w1 > 15) w1 = 15;
    const float fw = wwf - (float)w0;

    // ---- Stage w-interpolated slab (fp32 lerp, fp16 store): 216 groups ----
    const float4* g4 = (const float4*)grid;
    if (t < 216) {                          // 12c * 9h * 2 d-quads
        int c   = t / 18;
        int rem = t - c * 18;
        int h   = rem >> 1;
        int dq  = rem & 1;
        int base = ((b * CC + c) * HG + (hbase + h)) * 32;  // float4 off of [b,c,hg,0,0]
        float4 a  = g4[base + w0 * 2 + dq];
        float4 bb = g4[base + w1 * 2 + dq];
        int so = h * HSTRIDE_H + (dq * 4) * DSTRIDE_H + c;
        sh[so]                 = __float2half_rn(fmaf(fw, bb.x - a.x, a.x));
        sh[so + DSTRIDE_H]     = __float2half_rn(fmaf(fw, bb.y - a.y, a.y));
        sh[so + 2 * DSTRIDE_H] = __float2half_rn(fmaf(fw, bb.z - a.z, a.z));
        sh[so + 3 * DSTRIDE_H] = __float2half_rn(fmaf(fw, bb.w - a.w, a.w));
    }
    __syncthreads();

    // ---- Thread owns 2 consecutive columns ----
    const int j0 = half * 512 + t * 2;

    float2 gv = *(const float2*)(guide + ((size_t)b * HH + i) * WW_ + j0);
    float ga[2] = {gv.x, gv.y};

    float res[24];                          // res[c*2 + jj], constant indices only
    #pragma unroll
    for (int jj = 0; jj < 2; jj++) {
        float hhf = (float)(j0 + jj) * (15.0f / 1023.0f);
        int h0 = (int)hhf;
        int h1 = h0 + 1; if (h1 > 15) h1 = 15;
        const float fhj = hhf - (float)h0;
        const __half2 fh2 = __float2half2_rn(fhj);
        const int ho0 = (h0 - hbase) * HSTRIDE_B;
        const int ho1 = (h1 - hbase) * HSTRIDE_B;

        float dc  = ga[jj] * 7.0f;          // guide in [0,1) -> dc in [0,7)
        float dfl = floorf(dc);
        int d0 = (int)dfl;
        int d1 = d0 + 1; if (d1 > 7) d1 = 7;
        float dw = dc - dfl;
        const __half2 dw2 = __float2half2_rn(dw);

        const char* pA0 = sb + ho0 + d0 * DSTRIDE_B;   // (h0, d0)
        const char* pA1 = sb + ho0 + d1 * DSTRIDE_B;   // (h0, d1)
        const char* pB0 = sb + ho1 + d0 * DSTRIDE_B;   // (h1, d0)
        const char* pB1 = sb + ho1 + d1 * DSTRIDE_B;   // (h1, d1)

        #pragma unroll
        for (int qq = 0; qq < 3; qq++) {
            uint2 uA0 = *(const uint2*)(pA0 + 8 * qq);
            uint2 uA1 = *(const uint2*)(pA1 + 8 * qq);
            uint2 uB0 = *(const uint2*)(pB0 + 8 * qq);
            uint2 uB1 = *(const uint2*)(pB1 + 8 * qq);

            __half2 da0, da1, db0, db1;
            dlerp2(uA0, uA1, dw2, da0, da1);   // d-lerp at h0
            dlerp2(uB0, uB1, dw2, db0, db1);   // d-lerp at h1

            // h-blend in half2: r = da + fh*(db-da)
            __half2 hb0 = __hfma2(__hsub2(db0, da0), fh2, da0);
            __half2 hb1 = __hfma2(__hsub2(db1, da1), fh2, da1);

            float2 f0 = __half22float2(hb0);
            float2 f1 = __half22float2(hb1);

            const int c = qq * 4;
            res[(c + 0) * 2 + jj] = f0.x;
            res[(c + 1) * 2 + jj] = f0.y;
            res[(c + 2) * 2 + jj] = f1.x;
            res[(c + 3) * 2 + jj] = f1.y;
        }
    }

    // ---- Coalesced float2 stores: 12 channels ----
    #pragma unroll
    for (int c = 0; c < 12; c++) {
        float2 o = make_float2(res[c * 2 + 0], res[c * 2 + 1]);
        *(float2*)(out + (((size_t)b * CC + c) * HH + i) * WW_ + j0) = o;
    }
}

extern "C" void kernel_launch(void* const* d_in, const int* in_sizes, int n_in,
                              void* d_out, int out_size)
{
    const float* grid  = (const float*)d_in[0];
    const float* guide = (const float*)d_in[1];
    float* out = (float*)d_out;

    dim3 gr(HH * 2, 4);                     // two CTAs per (row, batch)
    bslice_kernel<<<gr, 256>>>(grid, guide, out);
}